// round 1
// baseline (speedup 1.0000x reference)
#include <cuda_runtime.h>
#include <math.h>

#define Bz   64
#define Tt   256
#define Vv   4096
#define Ee   512
#define Hh   1024
#define BT   (Bz*Tt)     // 16384
#define CAT  (Ee+Hh)     // 1536

// ---------------- static device scratch (no allocations allowed) ----------------
__device__ float    g_emb[BT * Ee];            // 32 MB   [bt][e]
__device__ float    g_pre[3u * BT * Hh];       // 192 MB  [gate][bt][n], gate 0=r,1=z,2=hbar
__device__ float    g_h[Bz * Hh];              // current hidden state [b][n]
__device__ float    g_rh[Bz * Hh];             // r * h
__device__ float    g_zz[Bz * Hh];             // z
__device__ float    g_hidden[BT * Hh];         // 64 MB   [bt][n]
__device__ unsigned g_bar[1024];               // grid-barrier counters

// ---------------- init: zero barrier counters, broadcast start -> h ----------------
__global__ void k_init(const float* __restrict__ start) {
    int i = blockIdx.x * blockDim.x + threadIdx.x;   // grid covers 65536
    if (i < Bz * Hh) g_h[i] = start[i & (Hh - 1)];
    if (i < 1024)    g_bar[i] = 0u;
}

// ---------------- embedding gather ----------------
__global__ void k_embed(const int* __restrict__ x, const float* __restrict__ wte) {
    int i  = blockIdx.x * blockDim.x + threadIdx.x;  // float4 index, total BT*Ee/4
    int bt = i >> 7;                                  // Ee/4 = 128 float4 per row
    int e4 = i & 127;
    int tok = x[bt];
    reinterpret_cast<float4*>(g_emb)[i] =
        reinterpret_cast<const float4*>(wte + (size_t)tok * Ee)[e4];
}

// ---------------- generic fp32 GEMM:  C[M,N] = A[M,K] * W[N,K]^T + bias ----------------
// tile 64x64, 256 threads, 4x4 per thread, Kt=32, k-major smem (all LDS are .128)
__global__ void __launch_bounds__(256) k_gemm(
    const float* __restrict__ A, int lda,
    const float* __restrict__ W, int ldw,
    const float* __restrict__ bias,
    float* __restrict__ C, int ldc, int K)
{
    __shared__ float As[32][64];
    __shared__ float Bs[32][64];

    const int tx = threadIdx.x & 15;       // col group
    const int ty = threadIdx.x >> 4;       // row group
    const int m0 = blockIdx.y * 64;
    const int n0 = blockIdx.x * 64;

    float acc[4][4] = {};

    for (int k0 = 0; k0 < K; k0 += 32) {
        // cooperative load: 512 float4 per tile per matrix, 2 per thread
        #pragma unroll
        for (int r = 0; r < 2; r++) {
            int q   = threadIdx.x + r * 256;
            int row = q >> 3;
            int kq  = (q & 7) << 2;
            float4 av = *reinterpret_cast<const float4*>(A + (size_t)(m0 + row) * lda + k0 + kq);
            As[kq + 0][row] = av.x; As[kq + 1][row] = av.y;
            As[kq + 2][row] = av.z; As[kq + 3][row] = av.w;
            float4 bv = *reinterpret_cast<const float4*>(W + (size_t)(n0 + row) * ldw + k0 + kq);
            Bs[kq + 0][row] = bv.x; Bs[kq + 1][row] = bv.y;
            Bs[kq + 2][row] = bv.z; Bs[kq + 3][row] = bv.w;
        }
        __syncthreads();

        #pragma unroll
        for (int kk = 0; kk < 32; kk++) {
            float4 a = *reinterpret_cast<float4*>(&As[kk][ty * 4]);
            float4 b = *reinterpret_cast<float4*>(&Bs[kk][tx * 4]);
            float av[4] = {a.x, a.y, a.z, a.w};
            float bv[4] = {b.x, b.y, b.z, b.w};
            #pragma unroll
            for (int i = 0; i < 4; i++)
                #pragma unroll
                for (int j = 0; j < 4; j++)
                    acc[i][j] = fmaf(av[i], bv[j], acc[i][j]);
        }
        __syncthreads();
    }

    #pragma unroll
    for (int i = 0; i < 4; i++) {
        int m = m0 + ty * 4 + i;
        int n = n0 + tx * 4;
        float4 o;
        o.x = acc[i][0] + bias[n + 0];
        o.y = acc[i][1] + bias[n + 1];
        o.z = acc[i][2] + bias[n + 2];
        o.w = acc[i][3] + bias[n + 3];
        *reinterpret_cast<float4*>(C + (size_t)m * ldc + n) = o;
    }
}

// ---------------- grid barrier (all blocks co-resident by construction) ----------------
__device__ __forceinline__ void gbarrier(int idx, unsigned G) {
    __syncthreads();
    if (threadIdx.x == 0) {
        __threadfence();
        unsigned a = atomicAdd(&g_bar[idx], 1u);
        if (a + 1u < G) {
            while (*reinterpret_cast<volatile unsigned*>(&g_bar[idx]) < G) { }
        }
        __threadfence();
    }
    __syncthreads();
}

// ---------------- persistent GRU scan ----------------
// grid = 128 blocks x 512 threads (co-resident on 148 SMs)
// phase1: r,z = sigmoid(pre + h @ Wg[:,E:]^T); write r*h and z
// phase2: hbar = tanh(pre + (r*h) @ Wbar[:,E:]^T); h = h + z*(hbar-h); store hidden[t]
__global__ void __launch_bounds__(512) k_scan(
    const float* __restrict__ Wr,
    const float* __restrict__ Wz,
    const float* __restrict__ Wbar)
{
    __shared__ float hs[64][32];
    __shared__ float ws[16][32];

    const int tid = threadIdx.x;
    const int g   = blockIdx.x;
    const unsigned G = gridDim.x;

    for (int t = 0; t < Tt; t++) {
        // ================= phase 1: gates r and z =================
        {
            const bool  isZ = (g >= 64);
            const int   n0  = (g & 63) * 16;
            const float* W  = isZ ? Wz : Wr;
            const float* pre = g_pre + (isZ ? (size_t)BT * Hh : (size_t)0);

            const int tx = tid & 15;       // column 0..15
            const int ty = tid >> 4;       // 0..31 -> rows 2ty, 2ty+1
            float acc0 = 0.f, acc1 = 0.f;

            for (int k0 = 0; k0 < Hh; k0 += 32) {
                int m  = tid >> 3;
                int kq = (tid & 7) << 2;
                *reinterpret_cast<float4*>(&hs[m][kq]) =
                    *reinterpret_cast<const float4*>(g_h + m * Hh + k0 + kq);
                int c  = tid >> 5;          // 0..15
                int kk = tid & 31;
                ws[c][kk] = W[(size_t)(n0 + c) * CAT + Ee + k0 + kk];
                __syncthreads();

                #pragma unroll
                for (int kk2 = 0; kk2 < 32; kk2 += 4) {
                    float4 a0 = *reinterpret_cast<float4*>(&hs[2 * ty][kk2]);
                    float4 a1 = *reinterpret_cast<float4*>(&hs[2 * ty + 1][kk2]);
                    float4 w4 = *reinterpret_cast<float4*>(&ws[tx][kk2]);
                    acc0 = fmaf(a0.x, w4.x, acc0); acc0 = fmaf(a0.y, w4.y, acc0);
                    acc0 = fmaf(a0.z, w4.z, acc0); acc0 = fmaf(a0.w, w4.w, acc0);
                    acc1 = fmaf(a1.x, w4.x, acc1); acc1 = fmaf(a1.y, w4.y, acc1);
                    acc1 = fmaf(a1.z, w4.z, acc1); acc1 = fmaf(a1.w, w4.w, acc1);
                }
                __syncthreads();
            }

            const int n = n0 + tx;
            #pragma unroll
            for (int i = 0; i < 2; i++) {
                int m = 2 * ty + i;
                float a = (i == 0) ? acc0 : acc1;
                float p = pre[(size_t)(m * Tt + t) * Hh + n];
                float gv = 1.f / (1.f + __expf(-(a + p)));
                if (!isZ) g_rh[m * Hh + n] = gv * g_h[m * Hh + n];
                else      g_zz[m * Hh + n] = gv;
            }
        }
        gbarrier(2 * t, G);

        // ================= phase 2: hbar + state update =================
        {
            const int n0 = g * 8;
            const int tx = tid & 7;        // column 0..7
            const int ty = tid >> 3;       // row 0..63
            float acc = 0.f;

            for (int k0 = 0; k0 < Hh; k0 += 32) {
                int m  = tid >> 3;
                int kq = (tid & 7) << 2;
                *reinterpret_cast<float4*>(&hs[m][kq]) =
                    *reinterpret_cast<const float4*>(g_rh + m * Hh + k0 + kq);
                if (tid < 256) {
                    int c  = tid >> 5;      // 0..7
                    int kk = tid & 31;
                    ws[c][kk] = Wbar[(size_t)(n0 + c) * CAT + Ee + k0 + kk];
                }
                __syncthreads();

                #pragma unroll
                for (int kk2 = 0; kk2 < 32; kk2 += 4) {
                    float4 a0 = *reinterpret_cast<float4*>(&hs[ty][kk2]);
                    float4 w4 = *reinterpret_cast<float4*>(&ws[tx][kk2]);
                    acc = fmaf(a0.x, w4.x, acc); acc = fmaf(a0.y, w4.y, acc);
                    acc = fmaf(a0.z, w4.z, acc); acc = fmaf(a0.w, w4.w, acc);
                }
                __syncthreads();
            }

            const int n = n0 + tx;
            const int m = ty;
            float p    = g_pre[(size_t)2 * BT * Hh + (size_t)(m * Tt + t) * Hh + n];
            float hbar = tanhf(acc + p);
            float z    = g_zz[m * Hh + n];
            float hp   = g_h[m * Hh + n];
            float hn   = fmaf(z, hbar - hp, hp);
            g_h[m * Hh + n] = hn;
            g_hidden[(size_t)(m * Tt + t) * Hh + n] = hn;
        }
        gbarrier(2 * t + 1, G);
    }
}

// ---------------- launch ----------------
extern "C" void kernel_launch(void* const* d_in, const int* in_sizes, int n_in,
                              void* d_out, int out_size)
{
    const int*   x     = (const int*)  d_in[0];
    const float* start = (const float*)d_in[1];
    const float* wte   = (const float*)d_in[2];
    const float* Wr    = (const float*)d_in[3];
    const float* br    = (const float*)d_in[4];
    const float* Wbar  = (const float*)d_in[5];
    const float* bbar  = (const float*)d_in[6];
    const float* Wz    = (const float*)d_in[7];
    const float* bz    = (const float*)d_in[8];
    const float* Whead = (const float*)d_in[9];
    const float* bhead = (const float*)d_in[10];
    float* out = (float*)d_out;

    float *p_emb, *p_pre, *p_hidden;
    cudaGetSymbolAddress((void**)&p_emb,    g_emb);
    cudaGetSymbolAddress((void**)&p_pre,    g_pre);
    cudaGetSymbolAddress((void**)&p_hidden, g_hidden);

    k_init<<<256, 256>>>(start);
    k_embed<<<(BT * Ee / 4) / 256, 256>>>(x, wte);

    // input projections (first E columns of each weight), pre[gate][bt][n]
    k_gemm<<<dim3(Hh / 64, BT / 64), 256>>>(p_emb, Ee, Wr,   CAT, br,   p_pre,                Hh, Ee);
    k_gemm<<<dim3(Hh / 64, BT / 64), 256>>>(p_emb, Ee, Wz,   CAT, bz,   p_pre + (size_t)BT*Hh, Hh, Ee);
    k_gemm<<<dim3(Hh / 64, BT / 64), 256>>>(p_emb, Ee, Wbar, CAT, bbar, p_pre + (size_t)2*BT*Hh, Hh, Ee);

    // sequential GRU scan (persistent)
    k_scan<<<128, 512>>>(Wr, Wz, Wbar);

    // LM head
    k_gemm<<<dim3(Vv / 64, BT / 64), 256>>>(p_hidden, Hh, Whead, Hh, bhead, out, Vv, Hh);
}